// round 2
// baseline (speedup 1.0000x reference)
#include <cuda_runtime.h>
#include <mma.h>
#include <math.h>

using namespace nvcuda;

// Problem constants
constexpr int Bsz  = 4096;   // batch
constexpr int Dsz  = 1024;   // input size
constexpr int Hsz  = 1024;   // hidden size
constexpr int KTOT = Dsz + Hsz;  // fused K = 2048

// Tiling
constexpr int BM = 128;      // batch rows per CTA
constexpr int BN = 128;      // 4 gates x 32 j-columns per CTA
constexpr int BK = 32;       // K per mainloop iter
constexpr int LDA = 36;      // padded smem stride (multiple of 4 floats, 144B rows -> 16B aligned)
constexpr int LDG = 132;     // padded epilogue gate-tile stride

// smem: mainloop uses As[128][36] + Ws[128][36] = 36864B
//       epilogue reuses the same region as G[128][132]  = 67584B
constexpr int SMEM_BYTES = BM * LDG * 4;  // 67584

__global__ __launch_bounds__(256, 2)
void lstm_fused_tf32_kernel(
    const float* __restrict__ x,     // [B, D]
    const float* __restrict__ h0,    // [B, H]
    const float* __restrict__ c0,    // [B, H]
    const float* __restrict__ w_ih,  // [4H, D]
    const float* __restrict__ w_hh,  // [4H, H]
    const float* __restrict__ b_ih,  // [4H]
    const float* __restrict__ b_hh,  // [4H]
    float* __restrict__ out)         // [2, B, H]  (h then c)
{
    extern __shared__ float smem[];
    float* As = smem;               // [BM][LDA]
    float* Ws = smem + BM * LDA;    // [BN][LDA]  (row n holds W-row for local gate/col, K-slice)

    const int jt  = blockIdx.x;     // j tile: 32 hidden columns
    const int mt  = blockIdx.y;     // m tile: 128 batch rows
    const int tid = threadIdx.x;
    const int warp = tid >> 5;
    const int wm = warp >> 2;       // 0..1  -> 64 M-rows per warp
    const int wn = warp & 3;        // 0..3  -> 32 N-cols per warp (one gate)

    wmma::fragment<wmma::accumulator, 16, 16, 8, float> c_frag[4][2];
    #pragma unroll
    for (int a = 0; a < 4; a++)
        #pragma unroll
        for (int b = 0; b < 2; b++)
            wmma::fill_fragment(c_frag[a][b], 0.0f);

    for (int kb = 0; kb < KTOT; kb += BK) {
        // Select source for this K slice (BK=32 divides both halves cleanly)
        const float* asrc = (kb < Dsz) ? (x    + kb) : (h0   + (kb - Dsz));
        const float* wsrc = (kb < Dsz) ? (w_ih + kb) : (w_hh + (kb - Dsz));

        // Load A tile: 128 rows x 32 cols, float4-vectorized, coalesced
        #pragma unroll
        for (int i = 0; i < 4; i++) {
            int q  = tid + i * 256;          // 0..1023 float4 slots
            int r  = q >> 3;                 // row 0..127
            int c4 = q & 7;                  // float4 column 0..7
            float4 v = *reinterpret_cast<const float4*>(
                asrc + (size_t)(mt * BM + r) * Dsz + c4 * 4);
            *reinterpret_cast<float4*>(&As[r * LDA + c4 * 4]) = v;
        }
        // Load W tile: local row n -> gate = n>>5, j = n&31 -> global W row gate*H + jt*32 + j
        #pragma unroll
        for (int i = 0; i < 4; i++) {
            int q  = tid + i * 256;
            int r  = q >> 3;
            int c4 = q & 7;
            int gate = r >> 5;
            int j    = r & 31;
            int nrow = gate * Hsz + jt * 32 + j;
            float4 v = *reinterpret_cast<const float4*>(
                wsrc + (size_t)nrow * Dsz + c4 * 4);
            *reinterpret_cast<float4*>(&Ws[r * LDA + c4 * 4]) = v;
        }
        __syncthreads();

        #pragma unroll
        for (int kk = 0; kk < BK; kk += 8) {
            wmma::fragment<wmma::matrix_a, 16, 16, 8, wmma::precision::tf32, wmma::row_major> a_frag[4];
            wmma::fragment<wmma::matrix_b, 16, 16, 8, wmma::precision::tf32, wmma::col_major> b_frag[2];
            #pragma unroll
            for (int im = 0; im < 4; im++) {
                wmma::load_matrix_sync(a_frag[im], &As[(wm * 64 + im * 16) * LDA + kk], LDA);
                #pragma unroll
                for (int t = 0; t < a_frag[im].num_elements; t++)
                    a_frag[im].x[t] = wmma::__float_to_tf32(a_frag[im].x[t]);
            }
            #pragma unroll
            for (int in = 0; in < 2; in++) {
                wmma::load_matrix_sync(b_frag[in], &Ws[(wn * 32 + in * 16) * LDA + kk], LDA);
                #pragma unroll
                for (int t = 0; t < b_frag[in].num_elements; t++)
                    b_frag[in].x[t] = wmma::__float_to_tf32(b_frag[in].x[t]);
            }
            #pragma unroll
            for (int im = 0; im < 4; im++)
                #pragma unroll
                for (int in = 0; in < 2; in++)
                    wmma::mma_sync(c_frag[im][in], a_frag[im], b_frag[in], c_frag[im][in]);
        }
        __syncthreads();
    }

    // ---- Epilogue: exchange gates through smem, apply LSTM nonlinearity ----
    float* G = smem;   // [BM][LDG] — reuses mainloop buffers (already synced)
    #pragma unroll
    for (int im = 0; im < 4; im++)
        #pragma unroll
        for (int in = 0; in < 2; in++)
            wmma::store_matrix_sync(&G[(wm * 64 + im * 16) * LDG + wn * 32 + in * 16],
                                    c_frag[im][in], LDG, wmma::mem_row_major);
    __syncthreads();

    // 128 rows x 32 j-cols = 4096 outputs, 16 per thread
    for (int idx = tid; idx < BM * 32; idx += 256) {
        int m  = idx >> 5;
        int j  = idx & 31;
        int row = mt * BM + m;
        int jg  = jt * 32 + j;

        float gi = G[m * LDG +      j] + b_ih[0 * Hsz + jg] + b_hh[0 * Hsz + jg];
        float gf = G[m * LDG + 32 + j] + b_ih[1 * Hsz + jg] + b_hh[1 * Hsz + jg];
        float gg = G[m * LDG + 64 + j] + b_ih[2 * Hsz + jg] + b_hh[2 * Hsz + jg];
        float go = G[m * LDG + 96 + j] + b_ih[3 * Hsz + jg] + b_hh[3 * Hsz + jg];

        float si = 1.0f / (1.0f + expf(-gi));
        float sf = 1.0f / (1.0f + expf(-gf));
        float so = 1.0f / (1.0f + expf(-go));
        float tg = tanhf(gg);

        float cold = c0[(size_t)row * Hsz + jg];
        float cn = sf * cold + si * tg;
        float hn = so * tanhf(cn);

        out[(size_t)row * Hsz + jg]                     = hn;   // h_new
        out[(size_t)Bsz * Hsz + (size_t)row * Hsz + jg] = cn;   // c_new
    }
}

extern "C" void kernel_launch(void* const* d_in, const int* in_sizes, int n_in,
                              void* d_out, int out_size) {
    const float* x    = (const float*)d_in[0];
    const float* h0   = (const float*)d_in[1];  // (1,B,H) -> flat B*H
    const float* c0   = (const float*)d_in[2];
    const float* w_ih = (const float*)d_in[3];
    const float* w_hh = (const float*)d_in[4];
    const float* b_ih = (const float*)d_in[5];
    const float* b_hh = (const float*)d_in[6];
    float* out = (float*)d_out;

    // Idempotent, host-side, not a stream op — safe under graph capture.
    cudaFuncSetAttribute(lstm_fused_tf32_kernel,
                         cudaFuncAttributeMaxDynamicSharedMemorySize, SMEM_BYTES);

    dim3 grid(Hsz / 32, Bsz / BM);   // (32 j-tiles, 32 m-tiles) = 1024 CTAs
    lstm_fused_tf32_kernel<<<grid, 256, SMEM_BYTES>>>(
        x, h0, c0, w_ih, w_hh, b_ih, b_hh, out);
}

// round 5
// speedup vs baseline: 3.0311x; 3.0311x over previous
#include <cuda_runtime.h>
#include <cuda_fp16.h>
#include <cstdint>
#include <mma.h>
#include <math.h>

using namespace nvcuda;

// Problem: gates[4096,4096] = [x|h0] @ [w_ih|w_hh]^T, then LSTM nonlinearity.
// B=4096, D=H=1024, fused K=2048.
constexpr int Bsz  = 4096;
constexpr int Hsz  = 1024;
constexpr int KTOT = 2048;

// GEMM tiling
constexpr int BM = 128;          // batch rows / CTA
constexpr int BK = 32;           // K per stage (fp16)
constexpr int NSTAGE = 3;
constexpr int LDA = 40;          // smem stride in halves (80B rows, 16B aligned)
constexpr int LDG = 132;         // epilogue gate-tile stride (floats)

constexpr int STAGE_HALVES = BM * LDA;            // per matrix per stage
// smem: 3 stages x (A + B) = 61440 B ; epilogue reuses as G[128][132] = 67584 B
constexpr int SMEM_BYTES = BM * LDG * 4;          // 67584

// fp16 scratch: A = [4096][2048] (x || h0), W = [4096][2048] (w_ih || w_hh)
__device__ __half g_Afp16[(size_t)Bsz * KTOT];
__device__ __half g_Wfp16[(size_t)(4 * Hsz) * KTOT];

// ── convert kernel: fuse + downconvert to fp16 ──────────────────────────────
__global__ void __launch_bounds__(256)
convert_kernel(const float* __restrict__ x,     // [4096,1024]
               const float* __restrict__ h0,    // [4096,1024]
               const float* __restrict__ w_ih,  // [4096,1024]
               const float* __restrict__ w_hh)  // [4096,1024]
{
    // each thread: one 8-half chunk of A and one of W
    const size_t t = (size_t)blockIdx.x * 256 + threadIdx.x;   // 0 .. 1M-1
    const size_t row = t >> 8;          // /256 chunks per row (2048/8)
    const size_t ck  = (t & 255) * 8;   // k offset, always within one half (1024%8==0)

    const float* asrc = (ck < 1024) ? (x    + ck) : (h0   + ck - 1024);
    const float* wsrc = (ck < 1024) ? (w_ih + ck) : (w_hh + ck - 1024);

    float4 a0 = *reinterpret_cast<const float4*>(asrc + row * 1024);
    float4 a1 = *reinterpret_cast<const float4*>(asrc + row * 1024 + 4);
    float4 w0 = *reinterpret_cast<const float4*>(wsrc + row * 1024);
    float4 w1 = *reinterpret_cast<const float4*>(wsrc + row * 1024 + 4);

    __half2 ha[4] = {
        __float22half2_rn(make_float2(a0.x, a0.y)),
        __float22half2_rn(make_float2(a0.z, a0.w)),
        __float22half2_rn(make_float2(a1.x, a1.y)),
        __float22half2_rn(make_float2(a1.z, a1.w))};
    __half2 hw[4] = {
        __float22half2_rn(make_float2(w0.x, w0.y)),
        __float22half2_rn(make_float2(w0.z, w0.w)),
        __float22half2_rn(make_float2(w1.x, w1.y)),
        __float22half2_rn(make_float2(w1.z, w1.w))};

    *reinterpret_cast<uint4*>(&g_Afp16[row * KTOT + ck]) = *reinterpret_cast<uint4*>(ha);
    *reinterpret_cast<uint4*>(&g_Wfp16[row * KTOT + ck]) = *reinterpret_cast<uint4*>(hw);
}

__device__ __forceinline__ void cp16(void* s, const void* g) {
    unsigned int sa = (unsigned int)__cvta_generic_to_shared(s);
    asm volatile("cp.async.cg.shared.global [%0], [%1], 16;"
                 :: "r"(sa), "l"(g) : "memory");
}

// ── fused GEMM + LSTM kernel ────────────────────────────────────────────────
__global__ void __launch_bounds__(256, 2)
lstm_fp16_kernel(const float* __restrict__ c0,
                 const float* __restrict__ b_ih,
                 const float* __restrict__ b_hh,
                 float* __restrict__ out)
{
    extern __shared__ __align__(16) char smraw[];
    __half* As[NSTAGE];
    __half* Ws[NSTAGE];
    #pragma unroll
    for (int s = 0; s < NSTAGE; s++) {
        As[s] = reinterpret_cast<__half*>(smraw) + (size_t)s * 2 * STAGE_HALVES;
        Ws[s] = As[s] + STAGE_HALVES;
    }

    const int jt  = blockIdx.x;      // 32 hidden cols per CTA
    const int mt  = blockIdx.y;      // 128 batch rows per CTA
    const int tid = threadIdx.x;
    const int warp = tid >> 5;
    const int wm = warp >> 2;        // 0..1 -> 64 M rows
    const int wn = warp & 3;         // 0..3 -> gate, 32 N cols

    const int aRow0 = mt * BM;

    wmma::fragment<wmma::accumulator, 16, 16, 16, float> c_frag[4][2];
    #pragma unroll
    for (int a = 0; a < 4; a++)
        #pragma unroll
        for (int b = 0; b < 2; b++)
            wmma::fill_fragment(c_frag[a][b], 0.0f);

    // stage loader: A rows 0..127 -> batch rows; W local row r -> gate=r>>5, j=r&31
    auto issue_stage = [&](int it, int s) {
        const size_t kb = (size_t)it * BK;
        #pragma unroll
        for (int i = 0; i < 2; i++) {
            int q  = tid + i * 256;        // 0..511 16B-slots
            int r  = q >> 2;               // row 0..127
            int c4 = q & 3;                // 16B col 0..3
            cp16(&As[s][r * LDA + c4 * 8],
                 &g_Afp16[(size_t)(aRow0 + r) * KTOT + kb + c4 * 8]);
        }
        #pragma unroll
        for (int i = 0; i < 2; i++) {
            int q  = tid + i * 256;
            int r  = q >> 2;
            int c4 = q & 3;
            int grow = (r >> 5) * Hsz + jt * 32 + (r & 31);
            cp16(&Ws[s][r * LDA + c4 * 8],
                 &g_Wfp16[(size_t)grow * KTOT + kb + c4 * 8]);
        }
        asm volatile("cp.async.commit_group;" ::: "memory");
    };

    constexpr int NIT = KTOT / BK;   // 64
    issue_stage(0, 0);
    issue_stage(1, 1);

    for (int it = 0; it < NIT; ++it) {
        asm volatile("cp.async.wait_group %0;" :: "n"(1) : "memory");
        __syncthreads();

        if (it + 2 < NIT) issue_stage(it + 2, (it + 2) % NSTAGE);

        const __half* as = As[it % NSTAGE];
        const __half* ws = Ws[it % NSTAGE];
        #pragma unroll
        for (int kk = 0; kk < BK; kk += 16) {
            wmma::fragment<wmma::matrix_a, 16, 16, 16, __half, wmma::row_major> a_frag[4];
            wmma::fragment<wmma::matrix_b, 16, 16, 16, __half, wmma::col_major> b_frag[2];
            #pragma unroll
            for (int im = 0; im < 4; im++)
                wmma::load_matrix_sync(a_frag[im], as + (wm * 64 + im * 16) * LDA + kk, LDA);
            #pragma unroll
            for (int in = 0; in < 2; in++)
                wmma::load_matrix_sync(b_frag[in], ws + (wn * 32 + in * 16) * LDA + kk, LDA);
            #pragma unroll
            for (int im = 0; im < 4; im++)
                #pragma unroll
                for (int in = 0; in < 2; in++)
                    wmma::mma_sync(c_frag[im][in], a_frag[im], b_frag[in], c_frag[im][in]);
        }
    }
    __syncthreads();

    // ── epilogue: exchange gates via smem, apply LSTM nonlinearity ──
    float* G = reinterpret_cast<float*>(smraw);   // [BM][LDG]
    #pragma unroll
    for (int im = 0; im < 4; im++)
        #pragma unroll
        for (int in = 0; in < 2; in++)
            wmma::store_matrix_sync(&G[(wm * 64 + im * 16) * LDG + wn * 32 + in * 16],
                                    c_frag[im][in], LDG, wmma::mem_row_major);
    __syncthreads();

    for (int idx = tid; idx < BM * 32; idx += 256) {
        int m  = idx >> 5;
        int j  = idx & 31;
        int row = mt * BM + m;
        int jg  = jt * 32 + j;

        float gi = G[m * LDG +      j] + b_ih[0 * Hsz + jg] + b_hh[0 * Hsz + jg];
        float gf = G[m * LDG + 32 + j] + b_ih[1 * Hsz + jg] + b_hh[1 * Hsz + jg];
        float gg = G[m * LDG + 64 + j] + b_ih[2 * Hsz + jg] + b_hh[2 * Hsz + jg];
        float go = G[m * LDG + 96 + j] + b_ih[3 * Hsz + jg] + b_hh[3 * Hsz + jg];

        float si = 1.0f / (1.0f + expf(-gi));
        float sf = 1.0f / (1.0f + expf(-gf));
        float so = 1.0f / (1.0f + expf(-go));
        float tg = tanhf(gg);

        float cold = c0[(size_t)row * Hsz + jg];
        float cn = sf * cold + si * tg;
        float hn = so * tanhf(cn);

        out[(size_t)row * Hsz + jg]                     = hn;
        out[(size_t)Bsz * Hsz + (size_t)row * Hsz + jg] = cn;
    }
}

extern "C" void kernel_launch(void* const* d_in, const int* in_sizes, int n_in,
                              void* d_out, int out_size) {
    const float* x    = (const float*)d_in[0];
    const float* h0   = (const float*)d_in[1];
    const float* c0   = (const float*)d_in[2];
    const float* w_ih = (const float*)d_in[3];
    const float* w_hh = (const float*)d_in[4];
    const float* b_ih = (const float*)d_in[5];
    const float* b_hh = (const float*)d_in[6];
    float* out = (float*)d_out;

    cudaFuncSetAttribute(lstm_fp16_kernel,
                         cudaFuncAttributeMaxDynamicSharedMemorySize, SMEM_BYTES);

    // 1) fuse + downconvert inputs to fp16 scratch
    //    4096 rows x 256 chunks = 1,048,576 threads -> 4096 blocks
    convert_kernel<<<4096, 256>>>(x, h0, w_ih, w_hh);

    // 2) fused GEMM + LSTM
    dim3 grid(Hsz / 32, Bsz / BM);   // (32, 32)
    lstm_fp16_kernel<<<grid, 256, SMEM_BYTES>>>(c0, b_ih, b_hh, out);
}

// round 6
// speedup vs baseline: 3.6179x; 1.1936x over previous
#include <cuda_runtime.h>
#include <cuda_fp16.h>
#include <cstdint>
#include <mma.h>
#include <math.h>

using namespace nvcuda;

// Problem: gates[4096,4096] = [x|h0] @ [w_ih|w_hh]^T, then LSTM nonlinearity.
// B=4096, D=H=1024, fused K=2048.
constexpr int Bsz  = 4096;
constexpr int Hsz  = 1024;
constexpr int KTOT = 2048;

// GEMM tiling
constexpr int BM = 128;          // batch rows / CTA
constexpr int BK = 64;           // K per stage (fp16)
constexpr int NSTAGE = 3;
constexpr int LDA = 72;          // smem stride in halves (144B rows, 16B aligned)
constexpr int LDG = 132;         // epilogue gate-tile stride (floats)

constexpr int STAGE_HALVES = BM * LDA;            // per matrix per stage (9216)
// smem: 3 stages x (A + B) = 110592 B ; epilogue G[128][132] = 67584 B reuses it
constexpr int SMEM_BYTES = NSTAGE * 2 * STAGE_HALVES * 2;   // 110592

// fp16 scratch: A = [4096][2048] (x || h0), W = [4096][2048] (w_ih || w_hh)
__device__ __half g_Afp16[(size_t)Bsz * KTOT];
__device__ __half g_Wfp16[(size_t)(4 * Hsz) * KTOT];

// ── convert kernel: fuse + downconvert to fp16 ──────────────────────────────
__global__ void __launch_bounds__(256)
convert_kernel(const float* __restrict__ x,     // [4096,1024]
               const float* __restrict__ h0,    // [4096,1024]
               const float* __restrict__ w_ih,  // [4096,1024]
               const float* __restrict__ w_hh)  // [4096,1024]
{
    const size_t t = (size_t)blockIdx.x * 256 + threadIdx.x;   // 0 .. 1M-1
    const size_t row = t >> 8;          // 256 8-half chunks per row
    const size_t ck  = (t & 255) * 8;   // k offset (1024 % 8 == 0: no straddle)

    const float* asrc = (ck < 1024) ? (x    + ck) : (h0   + ck - 1024);
    const float* wsrc = (ck < 1024) ? (w_ih + ck) : (w_hh + ck - 1024);

    float4 a0 = *reinterpret_cast<const float4*>(asrc + row * 1024);
    float4 a1 = *reinterpret_cast<const float4*>(asrc + row * 1024 + 4);
    float4 w0 = *reinterpret_cast<const float4*>(wsrc + row * 1024);
    float4 w1 = *reinterpret_cast<const float4*>(wsrc + row * 1024 + 4);

    __half2 ha[4] = {
        __float22half2_rn(make_float2(a0.x, a0.y)),
        __float22half2_rn(make_float2(a0.z, a0.w)),
        __float22half2_rn(make_float2(a1.x, a1.y)),
        __float22half2_rn(make_float2(a1.z, a1.w))};
    __half2 hw[4] = {
        __float22half2_rn(make_float2(w0.x, w0.y)),
        __float22half2_rn(make_float2(w0.z, w0.w)),
        __float22half2_rn(make_float2(w1.x, w1.y)),
        __float22half2_rn(make_float2(w1.z, w1.w))};

    *reinterpret_cast<uint4*>(&g_Afp16[row * KTOT + ck]) = *reinterpret_cast<uint4*>(ha);
    *reinterpret_cast<uint4*>(&g_Wfp16[row * KTOT + ck]) = *reinterpret_cast<uint4*>(hw);
}

__device__ __forceinline__ void cp16(void* s, const void* g) {
    unsigned int sa = (unsigned int)__cvta_generic_to_shared(s);
    asm volatile("cp.async.cg.shared.global [%0], [%1], 16;"
                 :: "r"(sa), "l"(g) : "memory");
}

// ── fused GEMM + LSTM kernel ────────────────────────────────────────────────
__global__ void __launch_bounds__(256, 2)
lstm_fp16_kernel(const float* __restrict__ c0,
                 const float* __restrict__ b_ih,
                 const float* __restrict__ b_hh,
                 float* __restrict__ out)
{
    extern __shared__ __align__(16) char smraw[];
    __half* As[NSTAGE];
    __half* Ws[NSTAGE];
    #pragma unroll
    for (int s = 0; s < NSTAGE; s++) {
        As[s] = reinterpret_cast<__half*>(smraw) + (size_t)s * 2 * STAGE_HALVES;
        Ws[s] = As[s] + STAGE_HALVES;
    }

    const int jt  = blockIdx.x;      // 32 hidden cols per CTA
    const int mt  = blockIdx.y;      // 128 batch rows per CTA
    const int tid = threadIdx.x;
    const int warp = tid >> 5;
    const int wm = warp >> 2;        // 0..1 -> 64 M rows
    const int wn = warp & 3;         // 0..3 -> gate, 32 N cols

    const int aRow0 = mt * BM;

    wmma::fragment<wmma::accumulator, 16, 16, 16, float> c_frag[4][2];
    #pragma unroll
    for (int a = 0; a < 4; a++)
        #pragma unroll
        for (int b = 0; b < 2; b++)
            wmma::fill_fragment(c_frag[a][b], 0.0f);

    // stage loader: 128 rows x 128B per matrix; 8 cp.async per thread total
    auto issue_stage = [&](int it, int s) {
        const size_t kb = (size_t)it * BK;
        #pragma unroll
        for (int i = 0; i < 4; i++) {
            int q  = tid + i * 256;        // 0..1023 16B-slots
            int r  = q >> 3;               // row 0..127
            int c4 = q & 7;                // 16B col 0..7
            cp16(&As[s][r * LDA + c4 * 8],
                 &g_Afp16[(size_t)(aRow0 + r) * KTOT + kb + c4 * 8]);
        }
        #pragma unroll
        for (int i = 0; i < 4; i++) {
            int q  = tid + i * 256;
            int r  = q >> 3;
            int c4 = q & 7;
            int grow = (r >> 5) * Hsz + jt * 32 + (r & 31);
            cp16(&Ws[s][r * LDA + c4 * 8],
                 &g_Wfp16[(size_t)grow * KTOT + kb + c4 * 8]);
        }
        asm volatile("cp.async.commit_group;" ::: "memory");
    };

    constexpr int NIT = KTOT / BK;   // 32
    issue_stage(0, 0);
    issue_stage(1, 1);

    for (int it = 0; it < NIT; ++it) {
        asm volatile("cp.async.wait_group %0;" :: "n"(1) : "memory");
        __syncthreads();

        const __half* as = As[it % NSTAGE];
        const __half* ws = Ws[it % NSTAGE];

        // kk block 0 first: get tensor pipe busy right after the barrier,
        // then stream next stage's cp.async under kk blocks 1..3.
        #pragma unroll
        for (int kk = 0; kk < BK; kk += 16) {
            wmma::fragment<wmma::matrix_a, 16, 16, 16, __half, wmma::row_major> a_frag[4];
            wmma::fragment<wmma::matrix_b, 16, 16, 16, __half, wmma::col_major> b_frag[2];
            #pragma unroll
            for (int im = 0; im < 4; im++)
                wmma::load_matrix_sync(a_frag[im], as + (wm * 64 + im * 16) * LDA + kk, LDA);
            #pragma unroll
            for (int in = 0; in < 2; in++)
                wmma::load_matrix_sync(b_frag[in], ws + (wn * 32 + in * 16) * LDA + kk, LDA);
            #pragma unroll
            for (int im = 0; im < 4; im++)
                #pragma unroll
                for (int in = 0; in < 2; in++)
                    wmma::mma_sync(c_frag[im][in], a_frag[im], b_frag[in], c_frag[im][in]);

            if (kk == 0 && it + 2 < NIT) issue_stage(it + 2, (it + 2) % NSTAGE);
        }
    }
    __syncthreads();

    // ── epilogue: exchange gates via smem, apply LSTM nonlinearity ──
    float* G = reinterpret_cast<float*>(smraw);   // [BM][LDG]
    #pragma unroll
    for (int im = 0; im < 4; im++)
        #pragma unroll
        for (int in = 0; in < 2; in++)
            wmma::store_matrix_sync(&G[(wm * 64 + im * 16) * LDG + wn * 32 + in * 16],
                                    c_frag[im][in], LDG, wmma::mem_row_major);
    __syncthreads();

    for (int idx = tid; idx < BM * 32; idx += 256) {
        int m  = idx >> 5;
        int j  = idx & 31;
        int row = mt * BM + m;
        int jg  = jt * 32 + j;

        float gi = G[m * LDG +      j] + b_ih[0 * Hsz + jg] + b_hh[0 * Hsz + jg];
        float gf = G[m * LDG + 32 + j] + b_ih[1 * Hsz + jg] + b_hh[1 * Hsz + jg];
        float gg = G[m * LDG + 64 + j] + b_ih[2 * Hsz + jg] + b_hh[2 * Hsz + jg];
        float go = G[m * LDG + 96 + j] + b_ih[3 * Hsz + jg] + b_hh[3 * Hsz + jg];

        float si = 1.0f / (1.0f + __expf(-gi));
        float sf = 1.0f / (1.0f + __expf(-gf));
        float so = 1.0f / (1.0f + __expf(-go));
        float tg = tanhf(gg);

        float cold = c0[(size_t)row * Hsz + jg];
        float cn = sf * cold + si * tg;
        float hn = so * tanhf(cn);

        out[(size_t)row * Hsz + jg]                     = hn;
        out[(size_t)Bsz * Hsz + (size_t)row * Hsz + jg] = cn;
    }
}

extern "C" void kernel_launch(void* const* d_in, const int* in_sizes, int n_in,
                              void* d_out, int out_size) {
    const float* x    = (const float*)d_in[0];
    const float* h0   = (const float*)d_in[1];
    const float* c0   = (const float*)d_in[2];
    const float* w_ih = (const float*)d_in[3];
    const float* w_hh = (const float*)d_in[4];
    const float* b_ih = (const float*)d_in[5];
    const float* b_hh = (const float*)d_in[6];
    float* out = (float*)d_out;

    cudaFuncSetAttribute(lstm_fp16_kernel,
                         cudaFuncAttributeMaxDynamicSharedMemorySize, SMEM_BYTES);

    // 1) fuse + downconvert inputs to fp16 scratch
    convert_kernel<<<4096, 256>>>(x, h0, w_ih, w_hh);

    // 2) fused GEMM + LSTM
    dim3 grid(Hsz / 32, Bsz / BM);   // (32, 32)
    lstm_fp16_kernel<<<grid, 256, SMEM_BYTES>>>(c0, b_ih, b_hh, out);
}